// round 1
// baseline (speedup 1.0000x reference)
#include <cuda_runtime.h>
#include <math.h>

#define Cc   4
#define Nn   50000
#define NNZe 800000
#define Ff   64
#define L0   128
#define EMBd 64
#define CN   (Cc*Nn)          // 200000
#define TOT  (Cc*NNZe)        // 3200000
#define NBLK ((CN+1023)/1024) // 196

// ---------------- scratch (static device allocations; no cudaMalloc) ----------------
__device__ int   g_is64;
__device__ int   g_deg[CN];
__device__ int   g_off[CN];
__device__ int   g_cursor[CN];
__device__ int   g_bsum[NBLK];
__device__ int   g_col[TOT];              // 12.8 MB
__device__ float g_S[Nn*256];             // 51.2 MB  [N, C*64] node-major
__device__ float g_h[Nn*128];             // 25.6 MB
__device__ float g_M[256*128];            // folded Ws@W0
__device__ float g_sum[128];
__device__ float g_sq[128];
__device__ float g_scale[128];
__device__ float g_shift[128];

// ---------------- helpers ----------------
__device__ __forceinline__ int load_idx(const void* A, long long pos, int is64) {
    if (is64) return (int)((const long long*)A)[pos];
    return ((const int*)A)[pos];
}

// ---------------- init: zero state + probe A dtype ----------------
__global__ void k_init(const void* __restrict__ A) {
    int idx = blockIdx.x * blockDim.x + threadIdx.x;
    if (idx < CN) g_deg[idx] = 0;
    if (idx < 128) { g_sum[idx] = 0.f; g_sq[idx] = 0.f; }
    if (idx == 0) {
        // int64 little-endian: high words (odd int32 slots) are all 0 (values in [0,N))
        const int* a32 = (const int*)A;
        int is64 = 1;
        for (int i = 0; i < 64; i++) if (a32[2*i+1] != 0) { is64 = 0; break; }
        g_is64 = is64;
    }
}

// ---------------- fold M[c*64+f, j] = sum_g Ws[c,f,g] * W0[c*64+g, j] ----------------
__global__ void k_fold(const float* __restrict__ Ws, const float* __restrict__ W0) {
    int idx = blockIdx.x * blockDim.x + threadIdx.x;   // 256*128
    if (idx >= 256*128) return;
    int r = idx >> 7, j = idx & 127;
    int c = r >> 6, f = r & 63;
    float acc = 0.f;
    #pragma unroll 16
    for (int g = 0; g < 64; g++)
        acc += Ws[(c*64 + f)*64 + g] * W0[(c*64 + g)*128 + j];
    g_M[idx] = acc;
}

// ---------------- degree histogram ----------------
__global__ void k_hist(const void* __restrict__ A) {
    int idx = blockIdx.x * blockDim.x + threadIdx.x;
    if (idx >= TOT) return;
    int is64 = g_is64;
    int c = idx / NNZe, e = idx - c*NNZe;
    long long pos = (long long)c * 2 * NNZe + e;       // dst array of category c
    int dst = load_idx(A, pos, is64);
    atomicAdd(&g_deg[c*Nn + dst], 1);
}

// ---------------- exclusive scan (3 stages) ----------------
__global__ void k_scan1() {
    __shared__ int sh[1024];
    int t = threadIdx.x;
    int idx = blockIdx.x * 1024 + t;
    int v = (idx < CN) ? g_deg[idx] : 0;
    sh[t] = v;
    __syncthreads();
    #pragma unroll
    for (int d = 1; d < 1024; d <<= 1) {
        int x = (t >= d) ? sh[t-d] : 0;
        __syncthreads();
        sh[t] += x;
        __syncthreads();
    }
    int incl = sh[t];
    if (idx < CN) g_off[idx] = incl - v;
    if (t == 1023) g_bsum[blockIdx.x] = incl;
}
__global__ void k_scan2() {
    if (threadIdx.x == 0) {
        int run = 0;
        for (int i = 0; i < NBLK; i++) { int t = g_bsum[i]; g_bsum[i] = run; run += t; }
    }
}
__global__ void k_scan3() {
    int idx = blockIdx.x * blockDim.x + threadIdx.x;
    if (idx >= CN) return;
    int o = g_off[idx] + g_bsum[idx >> 10];
    g_off[idx] = o;
    g_cursor[idx] = o;
}

// ---------------- CSR fill ----------------
__global__ void k_fill(const void* __restrict__ A) {
    int idx = blockIdx.x * blockDim.x + threadIdx.x;
    if (idx >= TOT) return;
    int is64 = g_is64;
    int c = idx / NNZe, e = idx - c*NNZe;
    long long base = (long long)c * 2 * NNZe;
    int dst = load_idx(A, base + e, is64);
    int src = load_idx(A, base + NNZe + e, is64);
    int p = atomicAdd(&g_cursor[c*Nn + dst], 1);
    g_col[p] = src;
}

// ---------------- aggregation: warp per (c,node), atomic-free ----------------
__global__ void k_agg(const float* __restrict__ X) {
    int w = (blockIdx.x * blockDim.x + threadIdx.x) >> 5;
    int lane = threadIdx.x & 31;
    if (w >= CN) return;
    int c = w / Nn, i = w - c*Nn;
    int start = g_off[w];
    int cnt = g_deg[w];
    const float2* X2 = (const float2*)X;   // each lane owns 2 consecutive feats
    float2 acc = make_float2(0.f, 0.f);
    int k = 0;
    for (; k + 4 <= cnt; k += 4) {
        int s0 = g_col[start+k], s1 = g_col[start+k+1];
        int s2 = g_col[start+k+2], s3 = g_col[start+k+3];
        float2 a = X2[s0*32 + lane], b = X2[s1*32 + lane];
        float2 cc = X2[s2*32 + lane], d = X2[s3*32 + lane];
        acc.x += a.x + b.x + cc.x + d.x;
        acc.y += a.y + b.y + cc.y + d.y;
    }
    for (; k < cnt; k++) {
        int s = g_col[start+k];
        float2 a = X2[s*32 + lane];
        acc.x += a.x; acc.y += a.y;
    }
    // S row-major [N, 256]; cat block c occupies cols [c*64, c*64+64)
    ((float2*)g_S)[i*128 + c*32 + lane] = acc;
}

// ---------------- GEMM1: h = S @ M + b0, fused BN stats ----------------
// block: 64 rows x 128 cols, 256 threads, thread = 8 rows x 4 cols
__global__ void __launch_bounds__(256) k_gemm1(const float* __restrict__ b0) {
    __shared__ float Msh[64*128];   // 32 KB
    __shared__ float Ssh[64*64];    // 16 KB (reused for BN reduce)
    int tid = threadIdx.x;
    int row0 = blockIdx.x * 64;
    int colg = tid & 31, rowg = tid >> 5;

    float acc[8][4];
    #pragma unroll
    for (int r = 0; r < 8; r++)
        #pragma unroll
        for (int j = 0; j < 4; j++) acc[r][j] = 0.f;

    for (int kb = 0; kb < 256; kb += 64) {
        for (int idx = tid; idx < 64*128; idx += 256) {
            int r = idx >> 7, j = idx & 127;
            Msh[idx] = g_M[(kb + r)*128 + j];
        }
        for (int idx = tid; idx < 64*64; idx += 256) {
            int r = idx >> 6, k = idx & 63;
            int row = row0 + r;
            Ssh[idx] = (row < Nn) ? g_S[row*256 + kb + k] : 0.f;
        }
        __syncthreads();
        const float4* M4 = (const float4*)Msh;
        #pragma unroll 8
        for (int k = 0; k < 64; k++) {
            float4 m = M4[k*32 + colg];
            #pragma unroll
            for (int rr = 0; rr < 8; rr++) {
                float s = Ssh[(rowg*8 + rr)*64 + k];
                acc[rr][0] += s*m.x; acc[rr][1] += s*m.y;
                acc[rr][2] += s*m.z; acc[rr][3] += s*m.w;
            }
        }
        __syncthreads();
    }

    float bb[4];
    #pragma unroll
    for (int j = 0; j < 4; j++) bb[j] = b0[colg*4 + j];

    float ps[4] = {0,0,0,0}, pq[4] = {0,0,0,0};
    #pragma unroll
    for (int rr = 0; rr < 8; rr++) {
        int row = row0 + rowg*8 + rr;
        if (row < Nn) {
            float4 v;
            v.x = acc[rr][0] + bb[0]; v.y = acc[rr][1] + bb[1];
            v.z = acc[rr][2] + bb[2]; v.w = acc[rr][3] + bb[3];
            ((float4*)g_h)[row*32 + colg] = v;
            ps[0]+=v.x; ps[1]+=v.y; ps[2]+=v.z; ps[3]+=v.w;
            pq[0]+=v.x*v.x; pq[1]+=v.y*v.y; pq[2]+=v.z*v.z; pq[3]+=v.w*v.w;
        }
    }
    // block reduce into shared (reuse Ssh), then one global atomic per column
    float* bs = Ssh; float* bq = Ssh + 128;
    if (tid < 128) { bs[tid] = 0.f; bq[tid] = 0.f; }
    __syncthreads();
    #pragma unroll
    for (int j = 0; j < 4; j++) {
        atomicAdd(&bs[colg*4 + j], ps[j]);
        atomicAdd(&bq[colg*4 + j], pq[j]);
    }
    __syncthreads();
    if (tid < 128) {
        atomicAdd(&g_sum[tid], bs[tid]);
        atomicAdd(&g_sq[tid],  bq[tid]);
    }
}

// ---------------- BN fold: scale/shift per column ----------------
__global__ void k_bn(const float* __restrict__ gamma, const float* __restrict__ beta) {
    int j = threadIdx.x;
    if (j >= 128) return;
    float m = g_sum[j] * (1.f / Nn);
    float v = g_sq[j] * (1.f / Nn) - m*m;
    float r = rsqrtf(v + 1e-5f);
    float sc = r * gamma[j];
    g_scale[j] = sc;
    g_shift[j] = beta[j] - m*sc;
}

// ---------------- GEMM2: out = ELU(BN(h)) @ W1 + b1 ----------------
// block: 4 rows x 64 cols, 256 threads
__global__ void __launch_bounds__(256) k_gemm2(const float* __restrict__ W1,
                                               const float* __restrict__ b1,
                                               float* __restrict__ out) {
    __shared__ float hs[4][128];
    int tid = threadIdx.x;
    int row0 = blockIdx.x * 4;
    for (int idx = tid; idx < 512; idx += 256) {
        int r = idx >> 7, k = idx & 127;
        int row = row0 + r;
        float v = 0.f;
        if (row < Nn) {
            v = g_h[row*128 + k] * g_scale[k] + g_shift[k];
            v = v > 0.f ? v : expm1f(v);
        }
        hs[r][k] = v;
    }
    __syncthreads();
    int r = tid >> 6, j = tid & 63;
    int row = row0 + r;
    float acc = b1[j];
    #pragma unroll 8
    for (int k = 0; k < 128; k++)
        acc += hs[r][k] * W1[k*64 + j];
    if (row < Nn) out[row*64 + j] = acc;
}

// ---------------- launch ----------------
extern "C" void kernel_launch(void* const* d_in, const int* in_sizes, int n_in,
                              void* d_out, int out_size) {
    const void*  A     = d_in[0];
    const float* X     = (const float*)d_in[1];
    const float* Ws    = (const float*)d_in[2];
    const float* W0    = (const float*)d_in[3];
    const float* b0    = (const float*)d_in[4];
    const float* gamma = (const float*)d_in[5];
    const float* beta  = (const float*)d_in[6];
    const float* W1    = (const float*)d_in[7];
    const float* b1    = (const float*)d_in[8];
    float* out = (float*)d_out;

    k_init<<<(CN + 255)/256, 256>>>(A);
    k_fold<<<(256*128)/256, 256>>>(Ws, W0);
    k_hist<<<(TOT + 255)/256, 256>>>(A);
    k_scan1<<<NBLK, 1024>>>();
    k_scan2<<<1, 32>>>();
    k_scan3<<<(CN + 255)/256, 256>>>();
    k_fill<<<(TOT + 255)/256, 256>>>(A);
    k_agg<<<(CN*32 + 255)/256, 256>>>(X);
    k_gemm1<<<(Nn + 63)/64, 256>>>(b0);
    k_bn<<<1, 128>>>(gamma, beta);
    k_gemm2<<<(Nn + 3)/4, 256>>>(W1, b1, out);
}

// round 2
// speedup vs baseline: 1.0628x; 1.0628x over previous
#include <cuda_runtime.h>
#include <math.h>

#define Cc   4
#define Nn   50000
#define NNZe 800000
#define CN   (Cc*Nn)          // 200000
#define TOT  (Cc*NNZe)        // 3200000
#define NBLK ((CN+1023)/1024) // 196
#define NROWB ((Nn+63)/64)    // 782

typedef unsigned long long u64;

// ---------------- scratch ----------------
__device__ int   g_is64;
__device__ int   g_deg[CN];
__device__ int   g_off[CN];
__device__ int   g_cursor[CN];
__device__ int   g_bsum[NBLK];
__device__ int   g_col[TOT];              // 12.8 MB
__device__ float g_h[Nn*128];             // 25.6 MB
__device__ float g_M[256*128];            // folded Ws@W0
__device__ float g_sum[128];
__device__ float g_sq[128];

// ---------------- packed f32x2 helpers ----------------
__device__ __forceinline__ u64 bcast2(float v) {
    u64 r; unsigned u = __float_as_uint(v);
    asm("mov.b64 %0, {%1, %1};" : "=l"(r) : "r"(u));
    return r;
}
__device__ __forceinline__ void fma2(u64& acc, u64 a, u64 b) {
    asm("fma.rn.f32x2 %0, %1, %2, %0;" : "+l"(acc) : "l"(a), "l"(b));
}
__device__ __forceinline__ float2 up2(u64 v) {
    unsigned lo, hi;
    asm("mov.b64 {%0, %1}, %2;" : "=r"(lo), "=r"(hi) : "l"(v));
    return make_float2(__uint_as_float(lo), __uint_as_float(hi));
}

// ---------------- prep: zero state, probe A dtype, fold M = Ws@W0 ----------------
__global__ void k_prep(const void* __restrict__ A,
                       const float* __restrict__ Ws, const float* __restrict__ W0) {
    int b = blockIdx.x;
    if (b < 782) {
        int idx = b * 256 + threadIdx.x;
        if (idx < CN) g_deg[idx] = 0;
        if (idx < 128) { g_sum[idx] = 0.f; g_sq[idx] = 0.f; }
        if (idx == 0) {
            const int* a32 = (const int*)A;
            int is64 = 1;
            for (int i = 0; i < 64; i++) if (a32[2*i+1] != 0) { is64 = 0; break; }
            g_is64 = is64;
        }
    } else {
        int idx = (b - 782) * 256 + threadIdx.x;   // 256*128 = 32768 elems
        if (idx >= 256*128) return;
        int r = idx >> 7, j = idx & 127;
        int c = r >> 6, f = r & 63;
        float acc = 0.f;
        #pragma unroll 16
        for (int g = 0; g < 64; g++)
            acc += Ws[(c*64 + f)*64 + g] * W0[(c*64 + g)*128 + j];
        g_M[idx] = acc;
    }
}

__device__ __forceinline__ int load_idx(const void* A, long long pos, int is64) {
    if (is64) return ((const int*)A)[pos*2];   // little-endian low word
    return ((const int*)A)[pos];
}

// ---------------- degree histogram ----------------
__global__ void k_hist(const void* __restrict__ A) {
    int idx = blockIdx.x * blockDim.x + threadIdx.x;
    if (idx >= TOT) return;
    int is64 = g_is64;
    int c = idx / NNZe, e = idx - c*NNZe;
    long long pos = (long long)c * 2 * NNZe + e;
    int dst = load_idx(A, pos, is64);
    atomicAdd(&g_deg[c*Nn + dst], 1);
}

// ---------------- scans ----------------
__global__ void k_scan1() {
    __shared__ int wsum[32];
    int t = threadIdx.x, idx = blockIdx.x * 1024 + t;
    int lane = t & 31, wd = t >> 5;
    int v = (idx < CN) ? g_deg[idx] : 0;
    int x = v;
    #pragma unroll
    for (int d = 1; d < 32; d <<= 1) { int y = __shfl_up_sync(~0u, x, d); if (lane >= d) x += y; }
    if (lane == 31) wsum[wd] = x;
    __syncthreads();
    if (wd == 0) {
        int s = wsum[lane];
        #pragma unroll
        for (int d = 1; d < 32; d <<= 1) { int y = __shfl_up_sync(~0u, s, d); if (lane >= d) s += y; }
        wsum[lane] = s;
    }
    __syncthreads();
    int incl = x + (wd > 0 ? wsum[wd-1] : 0);
    if (idx < CN) g_off[idx] = incl - v;
    if (t == 1023) g_bsum[blockIdx.x] = incl;
}
__global__ void k_scan2() {
    __shared__ int ws[8];
    int t = threadIdx.x, lane = t & 31, wd = t >> 5;
    int v = (t < NBLK) ? g_bsum[t] : 0;
    int x = v;
    #pragma unroll
    for (int d = 1; d < 32; d <<= 1) { int y = __shfl_up_sync(~0u, x, d); if (lane >= d) x += y; }
    if (lane == 31) ws[wd] = x;
    __syncthreads();
    int add = 0;
    #pragma unroll
    for (int i = 0; i < 8; i++) if (i < wd) add += ws[i];
    if (t < NBLK) g_bsum[t] = x + add - v;   // exclusive
}
__global__ void k_scan3() {
    int idx = blockIdx.x * blockDim.x + threadIdx.x;
    if (idx >= CN) return;
    int o = g_off[idx] + g_bsum[idx >> 10];
    g_off[idx] = o;
    g_cursor[idx] = o;
}

// ---------------- CSR fill ----------------
__global__ void k_fill(const void* __restrict__ A) {
    int idx = blockIdx.x * blockDim.x + threadIdx.x;
    if (idx >= TOT) return;
    int is64 = g_is64;
    int c = idx / NNZe, e = idx - c*NNZe;
    long long base = (long long)c * 2 * NNZe;
    int dst = load_idx(A, base + e, is64);
    int src = load_idx(A, base + NNZe + e, is64);
    int p = atomicAdd(&g_cursor[c*Nn + dst], 1);
    g_col[p] = src;
}

// ---------------- fused aggregation + GEMM1 (+ BN stats) ----------------
// block = 64 rows x 128 cols; 256 threads: colg=tid&31 (4 cols), rowg=tid>>5 (8 rows)
// K=256 in 4 tiles of 64 = 4 edge categories; each tile's S is gathered on the fly.
__global__ void __launch_bounds__(256, 2) k_aggemm(const float* __restrict__ X,
                                                   const float* __restrict__ b0) {
    __shared__ float Msh[64*128];   // 32 KB
    __shared__ float Ssh[64*64];    // 16 KB, [row][feat]; reused for BN reduce
    int tid = threadIdx.x, lane = tid & 31, wd = tid >> 5;
    int colg = tid & 31, rowg = tid >> 5;
    int row0 = blockIdx.x * 64;
    const float2* X2 = (const float2*)X;

    u64 acc[8][2];
    #pragma unroll
    for (int r = 0; r < 8; r++) { acc[r][0] = 0ull; acc[r][1] = 0ull; }

    for (int c = 0; c < 4; c++) {
        if (c > 0) __syncthreads();   // protect Msh/Ssh reuse
        // stage M tile (rows c*64 .. c*64+63)
        for (int idx = tid; idx < 64*128; idx += 256)
            Msh[idx] = g_M[c*64*128 + idx];
        // gather S tile: warp wd handles rows wd*8 .. wd*8+7
        #pragma unroll
        for (int rr = 0; rr < 8; rr++) {
            int r = wd*8 + rr;
            int node = row0 + r;
            float2 a2 = make_float2(0.f, 0.f);
            if (node < Nn) {
                int w = c*Nn + node;
                int start = g_off[w];
                int cnt = g_deg[w];
                const float2* Xr = X2 + lane;
                int k = 0;
                for (; k + 4 <= cnt; k += 4) {
                    int s0 = g_col[start+k],   s1 = g_col[start+k+1];
                    int s2 = g_col[start+k+2], s3 = g_col[start+k+3];
                    float2 v0 = Xr[s0*32], v1 = Xr[s1*32];
                    float2 v2 = Xr[s2*32], v3 = Xr[s3*32];
                    a2.x += (v0.x + v1.x) + (v2.x + v3.x);
                    a2.y += (v0.y + v1.y) + (v2.y + v3.y);
                }
                for (; k < cnt; k++) {
                    float2 v = Xr[g_col[start+k]*32];
                    a2.x += v.x; a2.y += v.y;
                }
            }
            *(float2*)&Ssh[r*64 + 2*lane] = a2;
        }
        __syncthreads();
        // compute: acc[rr][p] covers cols (4*colg+2p, 4*colg+2p+1), packed over cols
        const ulonglong2* M2 = (const ulonglong2*)Msh;
        #pragma unroll 4
        for (int k = 0; k < 64; k++) {
            ulonglong2 mm = M2[k*32 + colg];
            #pragma unroll
            for (int rr = 0; rr < 8; rr++) {
                u64 sv = bcast2(Ssh[(rowg*8 + rr)*64 + k]);
                fma2(acc[rr][0], sv, mm.x);
                fma2(acc[rr][1], sv, mm.y);
            }
        }
    }

    // epilogue: bias, store h, BN partial sums
    float4 bb = ((const float4*)b0)[colg];
    float ps0=0,ps1=0,ps2=0,ps3=0, pq0=0,pq1=0,pq2=0,pq3=0;
    #pragma unroll
    for (int rr = 0; rr < 8; rr++) {
        int row = row0 + rowg*8 + rr;
        if (row < Nn) {
            float2 v01 = up2(acc[rr][0]);
            float2 v23 = up2(acc[rr][1]);
            float4 v;
            v.x = v01.x + bb.x; v.y = v01.y + bb.y;
            v.z = v23.x + bb.z; v.w = v23.y + bb.w;
            ((float4*)g_h)[row*32 + colg] = v;
            ps0 += v.x; ps1 += v.y; ps2 += v.z; ps3 += v.w;
            pq0 += v.x*v.x; pq1 += v.y*v.y; pq2 += v.z*v.z; pq3 += v.w*v.w;
        }
    }
    __syncthreads();
    float* bs = Ssh;            // reuse
    float* bq = Ssh + 128;
    if (tid < 128) { bs[tid] = 0.f; bq[tid] = 0.f; }
    __syncthreads();
    atomicAdd(&bs[colg*4+0], ps0); atomicAdd(&bs[colg*4+1], ps1);
    atomicAdd(&bs[colg*4+2], ps2); atomicAdd(&bs[colg*4+3], ps3);
    atomicAdd(&bq[colg*4+0], pq0); atomicAdd(&bq[colg*4+1], pq1);
    atomicAdd(&bq[colg*4+2], pq2); atomicAdd(&bq[colg*4+3], pq3);
    __syncthreads();
    if (tid < 128) {
        atomicAdd(&g_sum[tid], bs[tid]);
        atomicAdd(&g_sq[tid],  bq[tid]);
    }
}

// ---------------- GEMM2: out = ELU(BN(h)) @ W1 + b1 (BN coeffs computed in-block) ----
// block = 64 rows x 64 cols; 256 threads: cq=tid&15 (4 cols), rg=tid>>4 (4 rows)
__global__ void __launch_bounds__(256, 2) k_gemm2(const float* __restrict__ W1,
                                                  const float* __restrict__ b1,
                                                  const float* __restrict__ gamma,
                                                  const float* __restrict__ beta,
                                                  float* __restrict__ out) {
    __shared__ float hs[64*128];   // 32 KB
    __shared__ float sc[128], sh[128];
    int tid = threadIdx.x;
    int cq = tid & 15, rg = tid >> 4;
    int row0 = blockIdx.x * 64;

    if (tid < 128) {
        float m = g_sum[tid] * (1.f / Nn);
        float var = g_sq[tid] * (1.f / Nn) - m*m;
        float r = rsqrtf(var + 1e-5f);
        float s = r * gamma[tid];
        sc[tid] = s;
        sh[tid] = beta[tid] - m*s;
    }
    __syncthreads();
    for (int idx = tid; idx < 64*128; idx += 256) {
        int r = idx >> 7, k = idx & 127;
        int row = row0 + r;
        float v = 0.f;
        if (row < Nn) {
            v = g_h[row*128 + k] * sc[k] + sh[k];
            v = v > 0.f ? v : expm1f(v);
        }
        hs[idx] = v;
    }
    __syncthreads();

    u64 acc[4][2];
    #pragma unroll
    for (int i = 0; i < 4; i++) { acc[i][0] = 0ull; acc[i][1] = 0ull; }
    const ulonglong2* W2 = (const ulonglong2*)W1;
    #pragma unroll 4
    for (int k = 0; k < 128; k++) {
        ulonglong2 ww = W2[k*16 + cq];
        #pragma unroll
        for (int i = 0; i < 4; i++) {
            u64 sv = bcast2(hs[(rg*4 + i)*128 + k]);
            fma2(acc[i][0], sv, ww.x);
            fma2(acc[i][1], sv, ww.y);
        }
    }
    float4 bb = ((const float4*)b1)[cq];
    #pragma unroll
    for (int i = 0; i < 4; i++) {
        int row = row0 + rg*4 + i;
        if (row < Nn) {
            float2 v01 = up2(acc[i][0]);
            float2 v23 = up2(acc[i][1]);
            float4 v;
            v.x = v01.x + bb.x; v.y = v01.y + bb.y;
            v.z = v23.x + bb.z; v.w = v23.y + bb.w;
            ((float4*)out)[row*16 + cq] = v;
        }
    }
}

// ---------------- launch ----------------
extern "C" void kernel_launch(void* const* d_in, const int* in_sizes, int n_in,
                              void* d_out, int out_size) {
    const void*  A     = d_in[0];
    const float* X     = (const float*)d_in[1];
    const float* Ws    = (const float*)d_in[2];
    const float* W0    = (const float*)d_in[3];
    const float* b0    = (const float*)d_in[4];
    const float* gamma = (const float*)d_in[5];
    const float* beta  = (const float*)d_in[6];
    const float* W1    = (const float*)d_in[7];
    const float* b1    = (const float*)d_in[8];
    float* out = (float*)d_out;

    k_prep<<<782 + 128, 256>>>(A, Ws, W0);
    k_hist<<<(TOT + 255)/256, 256>>>(A);
    k_scan1<<<NBLK, 1024>>>();
    k_scan2<<<1, 256>>>();
    k_scan3<<<(CN + 255)/256, 256>>>();
    k_fill<<<(TOT + 255)/256, 256>>>(A);
    k_aggemm<<<NROWB, 256>>>(X, b0);
    k_gemm2<<<NROWB, 256>>>(W1, b1, gamma, beta, out);
}